// round 12
// baseline (speedup 1.0000x reference)
#include <cuda_runtime.h>
#include <cuda_fp16.h>
#include <math.h>
#include <stdint.h>

#define Bsz 16
#define Ssz 512
#define Dsz 1024
#define Hh  16
#define Ff  4096
#define DH  64
#define MROWS (Bsz*Ssz)   // 8192

// ---------------- scratch (device-global; no allocation allowed) -------------
__device__ float g_X[MROWS*Dsz];
__device__ float g_Q[MROWS*Dsz];
__device__ float g_K[MROWS*Dsz];
__device__ float g_V[MROWS*Dsz];
__device__ float g_C[MROWS*Dsz];
__device__ float g_T[MROWS*Dsz];
__device__ float g_Hb[MROWS*Ff];        // reused as u32 Hh packed
__device__ uint32_t g_Ah[MROWS*Dsz/2];  // packed Xh [M][D/2]
__device__ uint32_t g_Bh[(Ff/2)*Dsz];   // packed weights [K/2][N]

// ---------------- helpers ----------------------------------------------------
__device__ __forceinline__ uint32_t packh2(float a, float b) {
    __half2 h = __floats2half2_rn(a, b);
    return *(uint32_t*)&h;
}
__device__ __forceinline__ void mma_f16(float& c0, float& c1, float& c2, float& c3,
                                        uint32_t a0, uint32_t a1, uint32_t a2, uint32_t a3,
                                        uint32_t b0, uint32_t b1) {
    asm volatile(
        "mma.sync.aligned.m16n8k16.row.col.f32.f16.f16.f32 "
        "{%0,%1,%2,%3}, {%4,%5,%6,%7}, {%8,%9}, {%0,%1,%2,%3};"
        : "+f"(c0), "+f"(c1), "+f"(c2), "+f"(c3)
        : "r"(a0), "r"(a1), "r"(a2), "r"(a3), "r"(b0), "r"(b1));
}
#define CP_ASYNC16(dst_u32, src_ptr) \
    asm volatile("cp.async.cg.shared.global [%0], [%1], 16;" \
                 :: "r"(dst_u32), "l"(src_ptr))
#define CP_COMMIT()  asm volatile("cp.async.commit_group;" ::: "memory")
#define CP_WAIT2()   asm volatile("cp.async.wait_group 2;" ::: "memory")
#define CP_WAIT1()   asm volatile("cp.async.wait_group 1;" ::: "memory")
#define CP_WAIT0()   asm volatile("cp.async.wait_group 0;" ::: "memory")
__device__ __forceinline__ uint32_t smem_u32(const void* p) {
    uint32_t a;
    asm("{ .reg .u64 t; cvta.to.shared.u64 t, %1; cvt.u32.u64 %0, t; }"
        : "=r"(a) : "l"(p));
    return a;
}

// ---------------- pack kernels ----------------------------------------------
__global__ void __launch_bounds__(256)
pack_a(const float* __restrict__ X, uint32_t* __restrict__ Y, int n2)
{
    int idx = blockIdx.x * 256 + threadIdx.x;
    if (idx < n2) {
        float2 v = ((const float2*)X)[idx];
        Y[idx] = packh2(v.x, v.y);
    }
}
__global__ void __launch_bounds__(256)
pack_w(const float* __restrict__ W, uint32_t* __restrict__ Y, int n2, int nshift)
{
    int idx = blockIdx.x * 256 + threadIdx.x;
    if (idx < n2) {
        int kp = idx >> nshift;
        int n  = idx & ((1 << nshift) - 1);
        size_t base = ((size_t)kp * 2 << nshift) + n;
        Y[idx] = packh2(W[base], W[base + (1 << nshift)]);
    }
}

// ---------------- fp16 mma GEMM (m16n8k16) -----------------------------------
#define APAD 12
#define BPAD 136
#define A_W  (128*APAD)
#define B_W  (8*BPAD)
#define STG_W (A_W + B_W)
#define GEMM_SMEM (4*STG_W*4)

template<bool RELU, bool RES, bool PACKH>
__global__ void __launch_bounds__(256, 2)
gemm_f16(const uint32_t* __restrict__ A, const uint32_t* __restrict__ Bm,
         const float* __restrict__ bias, const float* __restrict__ Res,
         float* __restrict__ C, int M, int N, int K)
{
    extern __shared__ uint32_t smu[];
    const uint32_t su = smem_u32(smu);

    const int tid  = threadIdx.x;
    const int warp = tid >> 5;
    const int lane = tid & 31;
    const int wm   = warp >> 2;
    const int wn   = warp & 3;
    const int g    = lane >> 2;
    const int tg   = lane & 3;

    const int bm = blockIdx.y * 128;
    const int bn = blockIdx.x * 128;
    const int K2 = K >> 1;
    const int NT = K >> 4;

    const int arow = tid >> 1;
    const int akc  = (tid & 1) * 4;
    const int bkr  = tid >> 5;
    const int bnc  = lane * 4;

    const uint32_t* Ap = A  + (size_t)(bm + arow) * K2 + akc;
    const uint32_t* Bp = Bm + (size_t)bkr * N + bn + bnc;

    auto issue_stage = [&](int s) {
        const int bi = s & 3;
        const uint32_t sA = su + (uint32_t)(bi * STG_W) * 4;
        const uint32_t sB = sA + A_W * 4;
        CP_ASYNC16(sA + (uint32_t)(arow * APAD + akc) * 4, Ap + s * 8);
        CP_ASYNC16(sB + (uint32_t)(bkr * BPAD + bnc) * 4, Bp + (size_t)s * 8 * N);
    };

    issue_stage(0); CP_COMMIT();
    issue_stage(1); CP_COMMIT();
    issue_stage(2); CP_COMMIT();

    float acc[4][4][4];
    #pragma unroll
    for (int i = 0; i < 4; ++i)
        #pragma unroll
        for (int j = 0; j < 4; ++j)
            #pragma unroll
            for (int e = 0; e < 4; ++e) acc[i][j][e] = 0.f;

    for (int t = 0; t < NT; ++t) {
        CP_WAIT2();
        __syncthreads();
        if (t + 3 < NT) issue_stage(t + 3);
        CP_COMMIT();

        const uint32_t* sA = smu + (t & 3) * STG_W;
        const uint32_t* sB = sA + A_W;

        uint32_t af[4][4];
        uint32_t bf[4][2];
        #pragma unroll
        for (int mi = 0; mi < 4; ++mi) {
            const int m0 = wm * 64 + mi * 16 + g;
            af[mi][0] = sA[m0 * APAD + tg];
            af[mi][1] = sA[(m0 + 8) * APAD + tg];
            af[mi][2] = sA[m0 * APAD + tg + 4];
            af[mi][3] = sA[(m0 + 8) * APAD + tg + 4];
        }
        #pragma unroll
        for (int nj = 0; nj < 4; ++nj) {
            const int cn = wn * 32 + nj * 8 + g;
            bf[nj][0] = sB[tg * BPAD + cn];
            bf[nj][1] = sB[(tg + 4) * BPAD + cn];
        }
        #pragma unroll
        for (int mi = 0; mi < 4; ++mi)
            #pragma unroll
            for (int nj = 0; nj < 4; ++nj)
                mma_f16(acc[mi][nj][0], acc[mi][nj][1], acc[mi][nj][2], acc[mi][nj][3],
                        af[mi][0], af[mi][1], af[mi][2], af[mi][3],
                        bf[nj][0], bf[nj][1]);
    }

    uint32_t* Ch = (uint32_t*)C;
    #pragma unroll
    for (int nj = 0; nj < 4; ++nj) {
        const int col = bn + wn * 32 + nj * 8 + 2 * tg;
        const float2 bi = *(const float2*)&bias[col];
        #pragma unroll
        for (int mi = 0; mi < 4; ++mi) {
            const int r0 = bm + wm * 64 + mi * 16 + g;
            const int r1 = r0 + 8;
            float2 o0 = make_float2(acc[mi][nj][0] + bi.x, acc[mi][nj][1] + bi.y);
            float2 o1 = make_float2(acc[mi][nj][2] + bi.x, acc[mi][nj][3] + bi.y);
            if (RES) {
                float2 q0 = *(const float2*)&Res[(size_t)r0 * N + col];
                float2 q1 = *(const float2*)&Res[(size_t)r1 * N + col];
                o0.x += q0.x; o0.y += q0.y;
                o1.x += q1.x; o1.y += q1.y;
            }
            if (RELU) {
                o0.x = fmaxf(o0.x, 0.f); o0.y = fmaxf(o0.y, 0.f);
                o1.x = fmaxf(o1.x, 0.f); o1.y = fmaxf(o1.y, 0.f);
            }
            if (PACKH) {
                Ch[(size_t)r0 * (N >> 1) + (col >> 1)] = packh2(o0.x, o0.y);
                Ch[(size_t)r1 * (N >> 1) + (col >> 1)] = packh2(o1.x, o1.y);
            } else {
                *(float2*)&C[(size_t)r0 * N + col] = o0;
                *(float2*)&C[(size_t)r1 * N + col] = o1;
            }
        }
    }
}

// ---------------- fp16 tensor-core flash attention ---------------------------
// grid (S/64, B*H), 256 thr = 8 warps: 4 q-tiles (wm, 16 rows) x 2 key-halves (wn, 32 keys).
// Inputs/outputs are half2-packed u32 [row][dpair]. Per-warp softmax streams,
// merged across wn pairs at the end.
#define AQW 2304            // Q smem: 64 rows x 36 u32
#define AKVW 4608           // K+V per buffer: 2 x 2304
#define ATT_SMEM ((AQW + 2*AKVW) * 4)   // 46080 B

__global__ void __launch_bounds__(256)
attn_f16(const uint32_t* __restrict__ Qg, const uint32_t* __restrict__ Kg,
         const uint32_t* __restrict__ Vg, uint32_t* __restrict__ Cg)
{
    extern __shared__ uint32_t smu[];
    uint32_t* Qs = smu;
    const uint32_t su = smem_u32(smu);

    const int tid  = threadIdx.x;
    const int warp = tid >> 5;
    const int lane = tid & 31;
    const int wm   = warp >> 1;     // 0..3
    const int wn   = warp & 1;      // 0..1
    const int g    = lane >> 2;
    const int tg   = lane & 3;
    const int qt   = blockIdx.x;    // 0..7
    const int bh   = blockIdx.y;
    const int b    = bh >> 4;
    const int h    = bh & 15;

    const size_t headoff = (size_t)b * Ssz * 512 + (size_t)h * 32;  // u32 elems

    // stage Q [64 x 32 u32]
    #pragma unroll
    for (int i = 0; i < 2; ++i) {
        int idx = tid + i * 256;
        int r = idx >> 3, c4 = (idx & 7) * 4;
        *(uint4*)&Qs[r * 36 + c4] =
            *(const uint4*)&Qg[headoff + (size_t)(qt * 64 + r) * 512 + c4];
    }

    auto issue = [&](int s) {
        const int buf = s & 1;
        #pragma unroll
        for (int i = 0; i < 2; ++i) {
            int idx = tid + i * 256;
            int r = idx >> 3, c4 = (idx & 7) * 4;
            size_t go = headoff + (size_t)(s * 64 + r) * 512 + c4;
            uint32_t dst = su + (uint32_t)(AQW + buf * AKVW + r * 36 + c4) * 4;
            CP_ASYNC16(dst, Kg + go);
            CP_ASYNC16(dst + 2304 * 4, Vg + go);
        }
    };

    float o[8][4];
    #pragma unroll
    for (int t = 0; t < 8; ++t)
        #pragma unroll
        for (int e = 0; e < 4; ++e) o[t][e] = 0.f;
    float m0 = -1e30f, m1 = -1e30f, l0 = 0.f, l1 = 0.f;

    const int qr = wm * 16;
    const int kc = wn * 32;

    issue(0); CP_COMMIT();

    for (int kb = 0; kb < 8; ++kb) {
        __syncthreads();             // prior-iter smem reads complete block-wide
        if (kb < 7) { issue(kb + 1); CP_COMMIT(); CP_WAIT1(); }
        else        { CP_WAIT0(); }
        __syncthreads();             // kb's K/V visible to all

        const uint32_t* Ks = smu + AQW + (kb & 1) * AKVW;
        const uint32_t* Vs = Ks + 2304;

        // S = Q @ K^T for this warp's 16 rows x 32 keys
        float s[4][4];
        #pragma unroll
        for (int nj = 0; nj < 4; ++nj)
            #pragma unroll
            for (int e = 0; e < 4; ++e) s[nj][e] = 0.f;
        #pragma unroll
        for (int ks = 0; ks < 4; ++ks) {
            uint32_t a0 = Qs[(qr + g) * 36 + ks * 8 + tg];
            uint32_t a1 = Qs[(qr + 8 + g) * 36 + ks * 8 + tg];
            uint32_t a2 = Qs[(qr + g) * 36 + ks * 8 + tg + 4];
            uint32_t a3 = Qs[(qr + 8 + g) * 36 + ks * 8 + tg + 4];
            #pragma unroll
            for (int nj = 0; nj < 4; ++nj) {
                const int key = kc + nj * 8 + g;
                uint32_t b0 = Ks[key * 36 + ks * 8 + tg];
                uint32_t b1 = Ks[key * 36 + ks * 8 + tg + 4];
                mma_f16(s[nj][0], s[nj][1], s[nj][2], s[nj][3], a0, a1, a2, a3, b0, b1);
            }
        }

        // scale + warp-local online softmax (rows g, g+8; quad reduce over tg)
        #pragma unroll
        for (int nj = 0; nj < 4; ++nj)
            #pragma unroll
            for (int e = 0; e < 4; ++e) s[nj][e] *= 0.125f;

        float r0mx = s[0][0], r1mx = s[0][2];
        #pragma unroll
        for (int nj = 0; nj < 4; ++nj) {
            r0mx = fmaxf(r0mx, fmaxf(s[nj][0], s[nj][1]));
            r1mx = fmaxf(r1mx, fmaxf(s[nj][2], s[nj][3]));
        }
        #pragma unroll
        for (int off = 1; off <= 2; off <<= 1) {
            r0mx = fmaxf(r0mx, __shfl_xor_sync(0xffffffffu, r0mx, off));
            r1mx = fmaxf(r1mx, __shfl_xor_sync(0xffffffffu, r1mx, off));
        }
        float mn0 = fmaxf(m0, r0mx), mn1 = fmaxf(m1, r1mx);
        float c0 = __expf(m0 - mn0), c1 = __expf(m1 - mn1);
        float sum0 = 0.f, sum1 = 0.f;
        #pragma unroll
        for (int nj = 0; nj < 4; ++nj) {
            s[nj][0] = __expf(s[nj][0] - mn0);
            s[nj][1] = __expf(s[nj][1] - mn0);
            s[nj][2] = __expf(s[nj][2] - mn1);
            s[nj][3] = __expf(s[nj][3] - mn1);
            sum0 += s[nj][0] + s[nj][1];
            sum1 += s[nj][2] + s[nj][3];
        }
        #pragma unroll
        for (int off = 1; off <= 2; off <<= 1) {
            sum0 += __shfl_xor_sync(0xffffffffu, sum0, off);
            sum1 += __shfl_xor_sync(0xffffffffu, sum1, off);
        }
        l0 = l0 * c0 + sum0; m0 = mn0;
        l1 = l1 * c1 + sum1; m1 = mn1;
        #pragma unroll
        for (int t = 0; t < 8; ++t) {
            o[t][0] *= c0; o[t][1] *= c0;
            o[t][2] *= c1; o[t][3] *= c1;
        }

        // pack P into A fragments (FA2 C->A correspondence)
        uint32_t pa[2][4];
        #pragma unroll
        for (int j = 0; j < 2; ++j) {
            pa[j][0] = packh2(s[2*j][0],   s[2*j][1]);
            pa[j][1] = packh2(s[2*j][2],   s[2*j][3]);
            pa[j][2] = packh2(s[2*j+1][0], s[2*j+1][1]);
            pa[j][3] = packh2(s[2*j+1][2], s[2*j+1][3]);
        }

        // O += P @ V (warp's 32 keys); V fragments via u16-pair loads
        const uint16_t* V16 = (const uint16_t*)Vs;   // [key][72 halves]
        #pragma unroll
        for (int j = 0; j < 2; ++j) {
            const int kr = kc + 16 * j + 2 * tg;
            #pragma unroll
            for (int t = 0; t < 8; ++t) {
                const int d = t * 8 + g;
                uint32_t b0 = (uint32_t)V16[kr * 72 + d]       | ((uint32_t)V16[(kr + 1) * 72 + d] << 16);
                uint32_t b1 = (uint32_t)V16[(kr + 8) * 72 + d] | ((uint32_t)V16[(kr + 9) * 72 + d] << 16);
                mma_f16(o[t][0], o[t][1], o[t][2], o[t][3],
                        pa[j][0], pa[j][1], pa[j][2], pa[j][3], b0, b1);
            }
        }
    }

    // merge wn pairs (rows shared by wn=0/1 warps of same wm)
    __syncthreads();
    float* Osm = (float*)smu;                 // [64 rows][68] (padded)
    float* Msm = (float*)(smu + 64 * 68);     // [64][2]
    const int r0 = wm * 16 + g;
    const int r1 = r0 + 8;
    if (wn == 1) {
        #pragma unroll
        for (int t = 0; t < 8; ++t) {
            Osm[r0 * 68 + t * 8 + 2 * tg]     = o[t][0];
            Osm[r0 * 68 + t * 8 + 2 * tg + 1] = o[t][1];
            Osm[r1 * 68 + t * 8 + 2 * tg]     = o[t][2];
            Osm[r1 * 68 + t * 8 + 2 * tg + 1] = o[t][3];
        }
        if (tg == 0) {
            Msm[r0 * 2] = m0; Msm[r0 * 2 + 1] = l0;
            Msm[r1 * 2] = m1; Msm[r1 * 2 + 1] = l1;
        }
    }
    __syncthreads();
    if (wn == 0) {
        float pm0 = Msm[r0 * 2], pl0 = Msm[r0 * 2 + 1];
        float pm1 = Msm[r1 * 2], pl1 = Msm[r1 * 2 + 1];
        float ms0 = fmaxf(m0, pm0), ms1 = fmaxf(m1, pm1);
        float f00 = __expf(m0 - ms0), f01 = __expf(pm0 - ms0);
        float f10 = __expf(m1 - ms1), f11 = __expf(pm1 - ms1);
        float inv0 = 1.f / (l0 * f00 + pl0 * f01);
        float inv1 = 1.f / (l1 * f10 + pl1 * f11);
        const size_t row0 = headoff + (size_t)(qt * 64 + r0) * 512;
        const size_t row1 = headoff + (size_t)(qt * 64 + r1) * 512;
        #pragma unroll
        for (int t = 0; t < 8; ++t) {
            float x0 = (o[t][0] * f00 + Osm[r0 * 68 + t * 8 + 2 * tg]     * f01) * inv0;
            float x1 = (o[t][1] * f00 + Osm[r0 * 68 + t * 8 + 2 * tg + 1] * f01) * inv0;
            float y0 = (o[t][2] * f10 + Osm[r1 * 68 + t * 8 + 2 * tg]     * f11) * inv1;
            float y1 = (o[t][3] * f10 + Osm[r1 * 68 + t * 8 + 2 * tg + 1] * f11) * inv1;
            Cg[row0 + t * 4 + tg] = packh2(x0, x1);
            Cg[row1 + t * 4 + tg] = packh2(y0, y1);
        }
    }
}

// ---------------- LayerNorm (fp32 out + packed out) --------------------------
__device__ __forceinline__ float block_sum(float v, float* red)
{
    #pragma unroll
    for (int off = 16; off; off >>= 1)
        v += __shfl_xor_sync(0xffffffffu, v, off);
    __syncthreads();
    if ((threadIdx.x & 31) == 0) red[threadIdx.x >> 5] = v;
    __syncthreads();
    return red[0]+red[1]+red[2]+red[3]+red[4]+red[5]+red[6]+red[7];
}

__global__ void __launch_bounds__(256)
ln_kernel(const float* __restrict__ X, const float* __restrict__ gw,
          const float* __restrict__ bw, float* __restrict__ Y,
          uint32_t* __restrict__ Yh)
{
    __shared__ float red[8];
    const int row = blockIdx.x;
    const int tid = threadIdx.x;
    const size_t base = (size_t)row * Dsz + tid * 4;

    float4 v = *(const float4*)&X[base];
    float mean = block_sum(v.x + v.y + v.z + v.w, red) * (1.f / Dsz);
    float dx = v.x - mean, dy = v.y - mean, dz = v.z - mean, dw = v.w - mean;
    float var = block_sum(dx*dx + dy*dy + dz*dz + dw*dw, red) * (1.f / Dsz);
    float inv = rsqrtf(var + 1e-6f);

    float4 g4 = *(const float4*)&gw[tid * 4];
    float4 b4 = *(const float4*)&bw[tid * 4];
    float4 o;
    o.x = dx * inv * g4.x + b4.x;
    o.y = dy * inv * g4.y + b4.y;
    o.z = dz * inv * g4.z + b4.z;
    o.w = dw * inv * g4.w + b4.w;
    *(float4*)&Y[base] = o;
    Yh[(size_t)row * 512 + tid * 2]     = packh2(o.x, o.y);
    Yh[(size_t)row * 512 + tid * 2 + 1] = packh2(o.z, o.w);
}

// ---------------- driver -----------------------------------------------------
extern "C" void kernel_launch(void* const* d_in, const int* in_sizes, int n_in,
                              void* d_out, int out_size)
{
    const float* hid  = (const float*)d_in[0];
    const float* Wq   = (const float*)d_in[1];
    const float* bq   = (const float*)d_in[2];
    const float* Wk   = (const float*)d_in[3];
    const float* bk   = (const float*)d_in[4];
    const float* Wv   = (const float*)d_in[5];
    const float* bv   = (const float*)d_in[6];
    const float* Wp   = (const float*)d_in[7];
    const float* bp   = (const float*)d_in[8];
    const float* g1   = (const float*)d_in[9];
    const float* be1  = (const float*)d_in[10];
    const float* W1   = (const float*)d_in[11];
    const float* b1   = (const float*)d_in[12];
    const float* W2   = (const float*)d_in[13];
    const float* b2   = (const float*)d_in[14];
    const float* g2   = (const float*)d_in[15];
    const float* be2  = (const float*)d_in[16];

    float *pX, *pQ, *pK, *pV, *pC, *pT, *pH;
    uint32_t *pXh, *pBh;
    cudaGetSymbolAddress((void**)&pX, g_X);
    cudaGetSymbolAddress((void**)&pQ, g_Q);
    cudaGetSymbolAddress((void**)&pK, g_K);
    cudaGetSymbolAddress((void**)&pV, g_V);
    cudaGetSymbolAddress((void**)&pC, g_C);
    cudaGetSymbolAddress((void**)&pT, g_T);
    cudaGetSymbolAddress((void**)&pH, g_Hb);
    cudaGetSymbolAddress((void**)&pXh, g_Ah);
    cudaGetSymbolAddress((void**)&pBh, g_Bh);
    uint32_t* pQh = (uint32_t*)pQ;
    uint32_t* pKh = (uint32_t*)pK;
    uint32_t* pVh = (uint32_t*)pV;
    uint32_t* pCh = (uint32_t*)pC;
    uint32_t* pHh = (uint32_t*)pH;

    cudaFuncSetAttribute(attn_f16,
                         cudaFuncAttributeMaxDynamicSharedMemorySize, ATT_SMEM);
    cudaFuncSetAttribute(gemm_f16<false,false,true>,
                         cudaFuncAttributeMaxDynamicSharedMemorySize, GEMM_SMEM);
    cudaFuncSetAttribute(gemm_f16<false,true,false>,
                         cudaFuncAttributeMaxDynamicSharedMemorySize, GEMM_SMEM);
    cudaFuncSetAttribute(gemm_f16<true,false,true>,
                         cudaFuncAttributeMaxDynamicSharedMemorySize, GEMM_SMEM);

    const size_t hbytes = sizeof(float) * (size_t)MROWS * Dsz;
    cudaMemcpyAsync(pX, hid, hbytes, cudaMemcpyDeviceToDevice);

    dim3 gD(Dsz / 128, MROWS / 128);   // (8, 64)
    dim3 gF(Ff  / 128, MROWS / 128);   // (32, 64)
    dim3 gA(Ssz / 64, Bsz * Hh);       // (8, 256)

    const int nXp  = MROWS * Dsz / 2;
    const int nWdd = (Dsz/2) * Dsz;
    const int nWdf = (Dsz/2) * Ff;
    const int nWfd = (Ff/2)  * Dsz;

    pack_a<<<nXp/256, 256>>>(pX, pXh, nXp);   // initial Xh

    for (int l = 0; l < 4; ++l) {
        const float* wq = Wq + (size_t)l * Dsz * Dsz;
        const float* wk = Wk + (size_t)l * Dsz * Dsz;
        const float* wv = Wv + (size_t)l * Dsz * Dsz;
        const float* wp = Wp + (size_t)l * Dsz * Dsz;
        const float* w1 = W1 + (size_t)l * Dsz * Ff;
        const float* w2 = W2 + (size_t)l * Ff * Dsz;

        // QKV -> packed fp16
        pack_w<<<nWdd/256, 256>>>(wq, pBh, nWdd, 10);
        gemm_f16<false,false,true><<<gD, 256, GEMM_SMEM>>>(pXh, pBh, bq + l*Dsz, nullptr, (float*)pQh, MROWS, Dsz, Dsz);
        pack_w<<<nWdd/256, 256>>>(wk, pBh, nWdd, 10);
        gemm_f16<false,false,true><<<gD, 256, GEMM_SMEM>>>(pXh, pBh, bk + l*Dsz, nullptr, (float*)pKh, MROWS, Dsz, Dsz);
        pack_w<<<nWdd/256, 256>>>(wv, pBh, nWdd, 10);
        gemm_f16<false,false,true><<<gD, 256, GEMM_SMEM>>>(pXh, pBh, bv + l*Dsz, nullptr, (float*)pVh, MROWS, Dsz, Dsz);

        attn_f16<<<gA, 256, ATT_SMEM>>>(pQh, pKh, pVh, pCh);

        // proj + LN1
        pack_w<<<nWdd/256, 256>>>(wp, pBh, nWdd, 10);
        gemm_f16<false,true,false><<<gD, 256, GEMM_SMEM>>>(pCh, pBh, bp + l*Dsz, pX, pT, MROWS, Dsz, Dsz);
        ln_kernel<<<MROWS, 256>>>(pT, g1 + l*Dsz, be1 + l*Dsz, pX, pXh);

        // FFN1 -> packed fp16 (ReLU)
        pack_w<<<nWdf/256, 256>>>(w1, pBh, nWdf, 12);
        gemm_f16<true,false,true><<<gF, 256, GEMM_SMEM>>>(pXh, pBh, b1 + l*Ff, nullptr, (float*)pHh, MROWS, Ff, Dsz);

        // FFN2 + LN2
        pack_w<<<nWfd/256, 256>>>(w2, pBh, nWfd, 10);
        gemm_f16<false,true,false><<<gD, 256, GEMM_SMEM>>>(pHh, pBh, b2 + l*Dsz, pX, pT, MROWS, Dsz, Ff);
        ln_kernel<<<MROWS, 256>>>(pT, g2 + l*Dsz, be2 + l*Dsz, pX, pXh);
    }

    cudaMemcpyAsync((float*)d_out, pX, hbytes, cudaMemcpyDeviceToDevice);
}